// round 2
// baseline (speedup 1.0000x reference)
#include <cuda_runtime.h>

#define BB 256
#define TT 2048
#define II 128
#define HH 256
#define AA 8

// 512MB scratch for xproj[b][t][h]  (b-major row index r = b*T + t)
__device__ float g_xproj[(size_t)BB * TT * HH];

// ---------------------------------------------------------------------------
// Kernel 1: xproj[r][j] = sum_k x[r][k] * W_ih[j][k]
// 256 threads (thread = output dim j), 256 rows per CTA, W_ih staged in smem
// as [j][132] (padded rows -> conflict-free float4 reads per thread).
// ---------------------------------------------------------------------------
__global__ void __launch_bounds__(256) xproj_kernel(
    const float* __restrict__ x, const float* __restrict__ W_ih) {
  extern __shared__ float smem[];
  float* sW = smem;                 // [256][132]
  float* sX = smem + 256 * 132;     // [4][128]
  const int tid = threadIdx.x;

  // Stage W_ih (coalesced global read, conflict-free per-thread row layout)
  #pragma unroll
  for (int idx = tid; idx < HH * II; idx += 256) {
    int j = idx >> 7, k = idx & 127;
    sW[j * 132 + k] = W_ih[idx];
  }
  __syncthreads();

  const size_t base_row = (size_t)blockIdx.x * 256;
  for (int chunk = 0; chunk < 64; ++chunk) {
    const size_t r0 = base_row + (size_t)chunk * 4;
    if (chunk) __syncthreads();
    // 4 consecutive rows of x = 512 consecutive floats (coalesced)
    #pragma unroll
    for (int idx = tid; idx < 4 * II; idx += 256) {
      sX[idx] = x[r0 * II + idx];
    }
    __syncthreads();

    float acc0 = 0.f, acc1 = 0.f, acc2 = 0.f, acc3 = 0.f;
    const float4* wrow = reinterpret_cast<const float4*>(sW + tid * 132);
    const float4* xv   = reinterpret_cast<const float4*>(sX);
    #pragma unroll
    for (int k4 = 0; k4 < 32; ++k4) {
      float4 w  = wrow[k4];
      float4 x0 = xv[k4];
      float4 x1 = xv[32 + k4];
      float4 x2 = xv[64 + k4];
      float4 x3 = xv[96 + k4];
      acc0 += w.x * x0.x + w.y * x0.y + w.z * x0.z + w.w * x0.w;
      acc1 += w.x * x1.x + w.y * x1.y + w.z * x1.z + w.w * x1.w;
      acc2 += w.x * x2.x + w.y * x2.y + w.z * x2.z + w.w * x2.w;
      acc3 += w.x * x3.x + w.y * x3.y + w.z * x3.z + w.w * x3.w;
    }
    float* outp = g_xproj + r0 * HH + tid;
    outp[0]      = acc0;
    outp[HH]     = acc1;
    outp[2 * HH] = acc2;
    outp[3 * HH] = acc3;
  }
}

// ---------------------------------------------------------------------------
// Kernel 2: recurrence. One CTA per 2 batch rows (128 CTAs), 256 threads
// (thread = output dim j). W_hh stored transposed: sWt[k][j] for k<208 in
// smem (padded stride 257 -> conflict-free), k in [208,256) in registers.
// h double-buffered in smem as float2 (b0,b1), one __syncthreads per step.
// Epilogue: write new_hx and compute actor/critic heads.
// ---------------------------------------------------------------------------
__global__ void __launch_bounds__(256) recurrence_kernel(
    const float* __restrict__ hx, const float* __restrict__ W_hh,
    const float* __restrict__ W_actor, const float* __restrict__ W_critic,
    float* __restrict__ out) {
  extern __shared__ float smem[];
  float*  sWt = smem;                                        // [208][257]
  float2* sh2 = reinterpret_cast<float2*>(smem + 208 * 257); // [2][256]
  const int tid = threadIdx.x;
  const int b0 = blockIdx.x * 2, b1 = b0 + 1;

  // Stage W_hh^T rows k<208 into smem (coalesced read, conflict-free STS)
  for (int idx = tid; idx < HH * HH; idx += 256) {
    int j = idx >> 8, k = idx & 255;
    if (k < 208) sWt[k * 257 + j] = W_hh[idx];
  }
  // Registers hold W_hh[j=tid][k=208..255]
  float wr[48];
  #pragma unroll
  for (int i = 0; i < 48; ++i) wr[i] = W_hh[tid * HH + 208 + i];

  // init h
  sh2[tid] = make_float2(hx[b0 * HH + tid], hx[b1 * HH + tid]);
  __syncthreads();

  const float* __restrict__ xp0 = g_xproj + (size_t)b0 * TT * HH + tid;
  const float* __restrict__ xp1 = g_xproj + (size_t)b1 * TT * HH + tid;
  float xa0 = __ldg(xp0);
  float xa1 = __ldg(xp1);

  int cur = 0;
  for (int t = 0; t < TT; ++t) {
    const float2* hc  = sh2 + cur * HH;
    const float4* hc4 = reinterpret_cast<const float4*>(hc);
    float acc0 = xa0, acc1 = xa1;
    // prefetch next timestep's input projection (hidden behind ~2k-cycle loop)
    if (t + 1 < TT) {
      xa0 = __ldg(xp0 + (size_t)(t + 1) * HH);
      xa1 = __ldg(xp1 + (size_t)(t + 1) * HH);
    }
    // smem-resident part of W (k = 0..207)
    #pragma unroll 8
    for (int k2 = 0; k2 < 104; ++k2) {
      float4 h = hc4[k2];
      float wA = sWt[(2 * k2) * 257 + tid];
      float wB = sWt[(2 * k2 + 1) * 257 + tid];
      acc0 += wA * h.x; acc1 += wA * h.y;
      acc0 += wB * h.z; acc1 += wB * h.w;
    }
    // register-resident part of W (k = 208..255)
    #pragma unroll
    for (int i = 0; i < 24; ++i) {
      float4 h = hc4[104 + i];
      acc0 += wr[2 * i]     * h.x; acc1 += wr[2 * i]     * h.y;
      acc0 += wr[2 * i + 1] * h.z; acc1 += wr[2 * i + 1] * h.w;
    }
    float2 hold = hc[tid];
    float2 hn;
    hn.x = 0.8f * hold.x + 0.2f * fmaxf(acc0, 0.0f);
    hn.y = 0.8f * hold.y + 0.2f * fmaxf(acc1, 0.0f);
    sh2[(cur ^ 1) * HH + tid] = hn;
    __syncthreads();
    cur ^= 1;
  }

  // -------- epilogue --------
  float* out_actor  = out;                 // [B][A]
  float* out_critic = out + BB * AA;       // [B]
  float* out_hx     = out + BB * AA + BB;  // [B][H]
  const float2* hf = sh2 + cur * HH;

  float2 hv = hf[tid];
  out_hx[b0 * HH + tid] = hv.x;
  out_hx[b1 * HH + tid] = hv.y;

  const int wid = tid >> 5, lane = tid & 31;
  // actor: warp w computes logit a=w for both batch rows
  float pa0 = 0.f, pa1 = 0.f;
  for (int j = lane; j < HH; j += 32) {
    float wa = W_actor[wid * HH + j];
    float2 h = hf[j];
    pa0 += wa * h.x;
    pa1 += wa * h.y;
  }
  #pragma unroll
  for (int off = 16; off; off >>= 1) {
    pa0 += __shfl_down_sync(0xffffffffu, pa0, off);
    pa1 += __shfl_down_sync(0xffffffffu, pa1, off);
  }
  if (lane == 0) {
    out_actor[b0 * AA + wid] = pa0;
    out_actor[b1 * AA + wid] = pa1;
  }
  // critic: warp 0
  if (wid == 0) {
    float pc0 = 0.f, pc1 = 0.f;
    for (int j = lane; j < HH; j += 32) {
      float wc = W_critic[j];
      float2 h = hf[j];
      pc0 += wc * h.x;
      pc1 += wc * h.y;
    }
    #pragma unroll
    for (int off = 16; off; off >>= 1) {
      pc0 += __shfl_down_sync(0xffffffffu, pc0, off);
      pc1 += __shfl_down_sync(0xffffffffu, pc1, off);
    }
    if (lane == 0) {
      out_critic[b0] = pc0;
      out_critic[b1] = pc1;
    }
  }
}

// ---------------------------------------------------------------------------
extern "C" void kernel_launch(void* const* d_in, const int* in_sizes, int n_in,
                              void* d_out, int out_size) {
  const float* x        = (const float*)d_in[0];
  const float* hx       = (const float*)d_in[1];
  const float* W_ih     = (const float*)d_in[2];
  const float* W_hh     = (const float*)d_in[3];
  const float* W_actor  = (const float*)d_in[4];
  const float* W_critic = (const float*)d_in[5];
  float* out = (float*)d_out;

  const int smem1 = (256 * 132 + 4 * 128) * (int)sizeof(float);          // 137216
  const int smem2 = 208 * 257 * (int)sizeof(float) + 2 * 256 * 8;        // 217920

  cudaFuncSetAttribute(xproj_kernel,
                       cudaFuncAttributeMaxDynamicSharedMemorySize, smem1);
  cudaFuncSetAttribute(recurrence_kernel,
                       cudaFuncAttributeMaxDynamicSharedMemorySize, smem2);

  // Phase 1: input projection for all (b,t)
  xproj_kernel<<<(BB * TT) / 256, 256, smem1>>>(x, W_ih);
  // Phase 2: sequential scan, batch-parallel across CTAs + heads + outputs
  recurrence_kernel<<<BB / 2, 256, smem2>>>(hx, W_hh, W_actor, W_critic, out);
}

// round 3
// speedup vs baseline: 1.4298x; 1.4298x over previous
#include <cuda_runtime.h>

#define BB 256
#define TT 2048
#define II 128
#define HH 256
#define AA 8

typedef unsigned long long ull;

// 512MB scratch for xproj[b][t][h]
__device__ float g_xproj[(size_t)BB * TT * HH];

__device__ __forceinline__ ull ffma2(ull a, ull b, ull c) {
  ull d;
  asm("fma.rn.f32x2 %0, %1, %2, %3;" : "=l"(d) : "l"(a), "l"(b), "l"(c));
  return d;
}
__device__ __forceinline__ ull pack2(float lo, float hi) {
  ull d;
  asm("mov.b64 %0, {%1, %2};" : "=l"(d) : "f"(lo), "f"(hi));
  return d;
}
__device__ __forceinline__ float hsum2(ull v) {
  float lo, hi;
  asm("mov.b64 {%0, %1}, %2;" : "=f"(lo), "=f"(hi) : "l"(v));
  return lo + hi;
}

// ---------------------------------------------------------------------------
// Kernel 1: xproj[r][j] = sum_k x[r][k] * W_ih[j][k]   (unchanged, ~1ms)
// ---------------------------------------------------------------------------
__global__ void __launch_bounds__(256) xproj_kernel(
    const float* __restrict__ x, const float* __restrict__ W_ih) {
  extern __shared__ float smem[];
  float* sW = smem;                 // [256][132]
  float* sX = smem + 256 * 132;     // [4][128]
  const int tid = threadIdx.x;

  #pragma unroll
  for (int idx = tid; idx < HH * II; idx += 256) {
    int j = idx >> 7, k = idx & 127;
    sW[j * 132 + k] = W_ih[idx];
  }
  __syncthreads();

  const size_t base_row = (size_t)blockIdx.x * 256;
  for (int chunk = 0; chunk < 64; ++chunk) {
    const size_t r0 = base_row + (size_t)chunk * 4;
    if (chunk) __syncthreads();
    #pragma unroll
    for (int idx = tid; idx < 4 * II; idx += 256) {
      sX[idx] = x[r0 * II + idx];
    }
    __syncthreads();

    float acc0 = 0.f, acc1 = 0.f, acc2 = 0.f, acc3 = 0.f;
    const float4* wrow = reinterpret_cast<const float4*>(sW + tid * 132);
    const float4* xv   = reinterpret_cast<const float4*>(sX);
    #pragma unroll
    for (int k4 = 0; k4 < 32; ++k4) {
      float4 w  = wrow[k4];
      float4 x0 = xv[k4];
      float4 x1 = xv[32 + k4];
      float4 x2 = xv[64 + k4];
      float4 x3 = xv[96 + k4];
      acc0 += w.x * x0.x + w.y * x0.y + w.z * x0.z + w.w * x0.w;
      acc1 += w.x * x1.x + w.y * x1.y + w.z * x1.z + w.w * x1.w;
      acc2 += w.x * x2.x + w.y * x2.y + w.z * x2.z + w.w * x2.w;
      acc3 += w.x * x3.x + w.y * x3.y + w.z * x3.z + w.w * x3.w;
    }
    float* outp = g_xproj + r0 * HH + tid;
    outp[0]      = acc0;
    outp[HH]     = acc1;
    outp[2 * HH] = acc2;
    outp[3 * HH] = acc3;
  }
}

// ---------------------------------------------------------------------------
// Kernel 2: recurrence. 128 CTAs x 256 threads, one CTA per batch pair.
// Thread (JP = tid&127, KH = tid>>7) computes j in {2JP, 2JP+1} over
// k in [128*KH, 128*KH+128). W: 80 floats/j in regs (ull pairs), 48/j via
// conflict-free LDS.128. h kept as two smem arrays, FFMA2 over k-pairs.
// Cross-k-half reduction via one float4 smem exchange per step.
// ---------------------------------------------------------------------------
__global__ void __launch_bounds__(256, 1) recurrence_kernel(
    const float* __restrict__ hx, const float* __restrict__ W_hh,
    const float* __restrict__ W_actor, const float* __restrict__ W_critic,
    float* __restrict__ out) {
  extern __shared__ float smem[];
  // layout: sW4 [2KH][2jsel][12q][128JP] float4 = 96KB, then h0,h1, partials
  float4* sW4  = reinterpret_cast<float4*>(smem);          // 24576 floats
  float*  sh0  = smem + 24576;                              // [256]
  float*  sh1  = sh0 + 256;                                 // [256]
  float4* spart = reinterpret_cast<float4*>(sh1 + 256);     // [128]

  const int tid = threadIdx.x;
  const int JP = tid & 127;
  const int KH = tid >> 7;
  const int j0 = 2 * JP, j1 = j0 + 1;
  const int kbase = KH * 128;
  const int b0 = blockIdx.x * 2, b1 = b0 + 1;

  // ---- stage W: registers (k = kbase .. kbase+79) ----
  ull wA[40], wB[40];
  {
    const float2* r0p = reinterpret_cast<const float2*>(W_hh + j0 * HH + kbase);
    const float2* r1p = reinterpret_cast<const float2*>(W_hh + j1 * HH + kbase);
    #pragma unroll
    for (int i = 0; i < 40; ++i) {
      float2 a = __ldg(r0p + i);
      float2 b = __ldg(r1p + i);
      wA[i] = pack2(a.x, a.y);
      wB[i] = pack2(b.x, b.y);
    }
  }
  // ---- stage W: smem (k = kbase+80 .. kbase+127), lane-contiguous float4 ----
  #pragma unroll
  for (int q = 0; q < 12; ++q) {
    sW4[(((KH * 2 + 0) * 12 + q) * 128) + JP] =
        *reinterpret_cast<const float4*>(W_hh + j0 * HH + kbase + 80 + 4 * q);
    sW4[(((KH * 2 + 1) * 12 + q) * 128) + JP] =
        *reinterpret_cast<const float4*>(W_hh + j1 * HH + kbase + 80 + 4 * q);
  }

  // ---- init h (finalizer threads own hold in regs) ----
  float hold00 = 0.f, hold10 = 0.f, hold01 = 0.f, hold11 = 0.f;
  if (KH == 0) {
    hold00 = hx[b0 * HH + j0];
    hold10 = hx[b0 * HH + j1];
    hold01 = hx[b1 * HH + j0];
    hold11 = hx[b1 * HH + j1];
    *reinterpret_cast<float2*>(sh0 + j0) = make_float2(hold00, hold10);
    *reinterpret_cast<float2*>(sh1 + j0) = make_float2(hold01, hold11);
  }
  __syncthreads();

  const float* xb0 = g_xproj + (size_t)b0 * TT * HH + j0;
  const float* xb1 = g_xproj + (size_t)b1 * TT * HH + j0;

  const float* hb0 = sh0 + kbase;
  const float* hb1 = sh1 + kbase;
  const ulonglong2* sWa = reinterpret_cast<const ulonglong2*>(
      sW4 + (KH * 2 + 0) * 12 * 128);
  const ulonglong2* sWb = reinterpret_cast<const ulonglong2*>(
      sW4 + (KH * 2 + 1) * 12 * 128);

  for (int t = 0; t < TT; ++t) {
    // prefetch this step's input projection (consumed after FMA phase)
    float2 xq0, xq1;
    if (KH == 0) {
      xq0 = __ldg(reinterpret_cast<const float2*>(xb0 + (size_t)t * HH));
      xq1 = __ldg(reinterpret_cast<const float2*>(xb1 + (size_t)t * HH));
    }

    ull acc00 = 0ull, acc10 = 0ull, acc01 = 0ull, acc11 = 0ull;
    #pragma unroll
    for (int q = 0; q < 32; ++q) {
      ulonglong2 h0 = *reinterpret_cast<const ulonglong2*>(hb0 + 4 * q);
      ulonglong2 h1 = *reinterpret_cast<const ulonglong2*>(hb1 + 4 * q);
      ull wa0, wa1, wb0, wb1;
      if (q < 20) {
        wa0 = wA[2 * q]; wa1 = wA[2 * q + 1];
        wb0 = wB[2 * q]; wb1 = wB[2 * q + 1];
      } else {
        ulonglong2 va = sWa[(q - 20) * 64 + (JP >> 1) * 1 + 0];  // placeholder, fixed below
        ulonglong2 vb;
        // proper indexing: float4 entry (q-20)*128 + JP, reinterpret as ulonglong2
        va = reinterpret_cast<const ulonglong2*>(sW4 + ((KH * 2 + 0) * 12 + (q - 20)) * 128)[JP];
        vb = reinterpret_cast<const ulonglong2*>(sW4 + ((KH * 2 + 1) * 12 + (q - 20)) * 128)[JP];
        wa0 = va.x; wa1 = va.y;
        wb0 = vb.x; wb1 = vb.y;
      }
      acc00 = ffma2(wa0, h0.x, acc00);
      acc10 = ffma2(wb0, h0.x, acc10);
      acc01 = ffma2(wa0, h1.x, acc01);
      acc11 = ffma2(wb0, h1.x, acc11);
      acc00 = ffma2(wa1, h0.y, acc00);
      acc10 = ffma2(wb1, h0.y, acc10);
      acc01 = ffma2(wa1, h1.y, acc01);
      acc11 = ffma2(wb1, h1.y, acc11);
    }

    float p00 = hsum2(acc00);  // (b0, j0) partial
    float p10 = hsum2(acc10);  // (b0, j1)
    float p01 = hsum2(acc01);  // (b1, j0)
    float p11 = hsum2(acc11);  // (b1, j1)

    if (KH == 1) {
      spart[JP] = make_float4(p00, p10, p01, p11);
    }
    __syncthreads();
    if (KH == 0) {
      float4 p = spart[JP];
      p00 += p.x + xq0.x;
      p10 += p.y + xq0.y;
      p01 += p.z + xq1.x;
      p11 += p.w + xq1.y;
      hold00 = 0.8f * hold00 + 0.2f * fmaxf(p00, 0.0f);
      hold10 = 0.8f * hold10 + 0.2f * fmaxf(p10, 0.0f);
      hold01 = 0.8f * hold01 + 0.2f * fmaxf(p01, 0.0f);
      hold11 = 0.8f * hold11 + 0.2f * fmaxf(p11, 0.0f);
      *reinterpret_cast<float2*>(sh0 + j0) = make_float2(hold00, hold10);
      *reinterpret_cast<float2*>(sh1 + j0) = make_float2(hold01, hold11);
    }
    __syncthreads();
  }

  // -------- epilogue --------
  float* out_actor  = out;                 // [B][A]
  float* out_critic = out + BB * AA;       // [B]
  float* out_hx     = out + BB * AA + BB;  // [B][H]

  out_hx[b0 * HH + tid] = sh0[tid];
  out_hx[b1 * HH + tid] = sh1[tid];

  const int wid = tid >> 5, lane = tid & 31;
  float pa0 = 0.f, pa1 = 0.f;
  for (int j = lane; j < HH; j += 32) {
    float wa = W_actor[wid * HH + j];
    pa0 += wa * sh0[j];
    pa1 += wa * sh1[j];
  }
  #pragma unroll
  for (int off = 16; off; off >>= 1) {
    pa0 += __shfl_down_sync(0xffffffffu, pa0, off);
    pa1 += __shfl_down_sync(0xffffffffu, pa1, off);
  }
  if (lane == 0) {
    out_actor[b0 * AA + wid] = pa0;
    out_actor[b1 * AA + wid] = pa1;
  }
  if (wid == 0) {
    float pc0 = 0.f, pc1 = 0.f;
    for (int j = lane; j < HH; j += 32) {
      float wc = W_critic[j];
      pc0 += wc * sh0[j];
      pc1 += wc * sh1[j];
    }
    #pragma unroll
    for (int off = 16; off; off >>= 1) {
      pc0 += __shfl_down_sync(0xffffffffu, pc0, off);
      pc1 += __shfl_down_sync(0xffffffffu, pc1, off);
    }
    if (lane == 0) {
      out_critic[b0] = pc0;
      out_critic[b1] = pc1;
    }
  }
}

// ---------------------------------------------------------------------------
extern "C" void kernel_launch(void* const* d_in, const int* in_sizes, int n_in,
                              void* d_out, int out_size) {
  const float* x        = (const float*)d_in[0];
  const float* hx       = (const float*)d_in[1];
  const float* W_ih     = (const float*)d_in[2];
  const float* W_hh     = (const float*)d_in[3];
  const float* W_actor  = (const float*)d_in[4];
  const float* W_critic = (const float*)d_in[5];
  float* out = (float*)d_out;

  const int smem1 = (256 * 132 + 4 * 128) * (int)sizeof(float);   // 137216
  const int smem2 = (24576 + 256 + 256 + 512) * (int)sizeof(float); // 102400

  cudaFuncSetAttribute(xproj_kernel,
                       cudaFuncAttributeMaxDynamicSharedMemorySize, smem1);
  cudaFuncSetAttribute(recurrence_kernel,
                       cudaFuncAttributeMaxDynamicSharedMemorySize, smem2);

  xproj_kernel<<<(BB * TT) / 256, 256, smem1>>>(x, W_ih);
  recurrence_kernel<<<BB / 2, 256, smem2>>>(hx, W_hh, W_actor, W_critic, out);
}

// round 4
// speedup vs baseline: 1.4720x; 1.0295x over previous
#include <cuda_runtime.h>

#define BB 256
#define TT 2048
#define II 128
#define HH 256
#define AA 8

typedef unsigned long long ull;

// 512MB scratch for xproj[b][t][h]
__device__ float g_xproj[(size_t)BB * TT * HH];

__device__ __forceinline__ ull ffma2(ull a, ull b, ull c) {
  ull d;
  asm("fma.rn.f32x2 %0, %1, %2, %3;" : "=l"(d) : "l"(a), "l"(b), "l"(c));
  return d;
}
__device__ __forceinline__ ull pack2(float lo, float hi) {
  ull d;
  asm("mov.b64 %0, {%1, %2};" : "=l"(d) : "f"(lo), "f"(hi));
  return d;
}
__device__ __forceinline__ float hsum2(ull v) {
  float lo, hi;
  asm("mov.b64 {%0, %1}, %2;" : "=f"(lo), "=f"(hi) : "l"(v));
  return lo + hi;
}

// ---------------------------------------------------------------------------
// Kernel 1: xproj[r][j] = sum_k x[r][k] * W_ih[j][k]
// 256 threads, thread = j. W_ih row lives in 64 ull REGISTERS (no smem W, no
// bank conflicts). x staged in double-buffered smem chunks of 16 rows; all
// x reads are warp-broadcast LDS.128. f32x2 FMAs. One sync per chunk.
// ---------------------------------------------------------------------------
__global__ void __launch_bounds__(256) xproj_kernel(
    const float* __restrict__ x, const float* __restrict__ W_ih) {
  extern __shared__ float smem[];  // 2 x 2048 floats (16KB)
  const int tid = threadIdx.x;
  const int j = tid;

  // W_ih[j][*] -> 64 ull regs (k-pairs)
  ull w[64];
  const float2* wp = reinterpret_cast<const float2*>(W_ih + j * II);
  #pragma unroll
  for (int i = 0; i < 64; ++i) {
    float2 v = __ldg(wp + i);
    w[i] = pack2(v.x, v.y);
  }

  const size_t rowbase = (size_t)blockIdx.x * 256;
  const float* xbase = x + rowbase * II;

  // prefetch + stage chunk 0 (2048 floats = 512 float4)
  float4 pf0 = __ldg(reinterpret_cast<const float4*>(xbase) + tid);
  float4 pf1 = __ldg(reinterpret_cast<const float4*>(xbase) + 256 + tid);
  reinterpret_cast<float4*>(smem)[tid] = pf0;
  reinterpret_cast<float4*>(smem)[256 + tid] = pf1;
  __syncthreads();

  for (int c = 0; c < 16; ++c) {
    const float* sX = smem + (c & 1) * 2048;
    float* sXn = smem + ((c + 1) & 1) * 2048;
    if (c < 15) {
      pf0 = __ldg(reinterpret_cast<const float4*>(xbase + (c + 1) * 2048) + tid);
      pf1 = __ldg(reinterpret_cast<const float4*>(xbase + (c + 1) * 2048) + 256 + tid);
    }
    float* op = g_xproj + (rowbase + (size_t)c * 16) * HH + j;
    #pragma unroll
    for (int r = 0; r < 16; ++r) {
      const ulonglong2* xr =
          reinterpret_cast<const ulonglong2*>(sX + r * II);
      ull a0 = 0ull, a1 = 0ull;
      #pragma unroll
      for (int k4 = 0; k4 < 32; k4 += 2) {
        ulonglong2 xv0 = xr[k4];
        ulonglong2 xv1 = xr[k4 + 1];
        a0 = ffma2(w[2 * k4],     xv0.x, a0);
        a0 = ffma2(w[2 * k4 + 1], xv0.y, a0);
        a1 = ffma2(w[2 * k4 + 2], xv1.x, a1);
        a1 = ffma2(w[2 * k4 + 3], xv1.y, a1);
      }
      op[r * HH] = hsum2(a0) + hsum2(a1);
    }
    if (c < 15) {
      reinterpret_cast<float4*>(sXn)[tid] = pf0;
      reinterpret_cast<float4*>(sXn)[256 + tid] = pf1;
      __syncthreads();
    }
  }
}

// ---------------------------------------------------------------------------
// Kernel 2: recurrence. 128 CTAs x 512 threads, one CTA per batch pair.
// Thread (JP = tid&127, KH = tid>>7 in 0..3) computes j in {2JP,2JP+1} over
// k in [64*KH, 64*KH+64). W per thread: 80 floats in regs (40 ull) +
// 48 floats via conflict-free lane-spread LDS.128. h double arrays in smem,
// broadcast ulonglong2 loads, f32x2 FMAs. 4-way k-reduction via one float4
// smem exchange; KH==0 warps finalize (hold in regs) and store new h.
// ---------------------------------------------------------------------------
__global__ void __launch_bounds__(512, 1) recurrence_kernel(
    const float* __restrict__ hx, const float* __restrict__ W_hh,
    const float* __restrict__ W_actor, const float* __restrict__ W_critic,
    float* __restrict__ out) {
  extern __shared__ float smem[];
  // sW: 24576 floats (98304B): [KH(4)][jsel(2)][q(6)][JP(128)] float4
  float4* sW4   = reinterpret_cast<float4*>(smem);
  float*  sh0   = smem + 24576;                        // [256]
  float*  sh1   = sh0 + 256;                           // [256]
  float4* spart = reinterpret_cast<float4*>(sh1 + 256);  // [3][128]

  const int tid = threadIdx.x;
  const int JP = tid & 127;
  const int KH = tid >> 7;
  const int j0 = 2 * JP, j1 = j0 + 1;
  const int kb = KH * 64;
  const int b0 = blockIdx.x * 2, b1 = b0 + 1;

  // ---- stage W regs: k in [kb, kb+40) ----
  ull wA[20], wB[20];
  {
    const float2* r0p = reinterpret_cast<const float2*>(W_hh + j0 * HH + kb);
    const float2* r1p = reinterpret_cast<const float2*>(W_hh + j1 * HH + kb);
    #pragma unroll
    for (int i = 0; i < 20; ++i) {
      float2 a = __ldg(r0p + i);
      float2 b = __ldg(r1p + i);
      wA[i] = pack2(a.x, a.y);
      wB[i] = pack2(b.x, b.y);
    }
  }
  // ---- stage W smem: k in [kb+40, kb+64) = 6 float4 per j ----
  #pragma unroll
  for (int q = 0; q < 6; ++q) {
    sW4[((KH * 2 + 0) * 6 + q) * 128 + JP] =
        *reinterpret_cast<const float4*>(W_hh + j0 * HH + kb + 40 + 4 * q);
    sW4[((KH * 2 + 1) * 6 + q) * 128 + JP] =
        *reinterpret_cast<const float4*>(W_hh + j1 * HH + kb + 40 + 4 * q);
  }

  // ---- init h (hold lives in KH0 registers) ----
  float h00 = 0.f, h10 = 0.f, h01 = 0.f, h11 = 0.f;
  if (KH == 0) {
    h00 = hx[b0 * HH + j0];
    h10 = hx[b0 * HH + j1];
    h01 = hx[b1 * HH + j0];
    h11 = hx[b1 * HH + j1];
    *reinterpret_cast<float2*>(sh0 + j0) = make_float2(h00, h10);
    *reinterpret_cast<float2*>(sh1 + j0) = make_float2(h01, h11);
  }
  __syncthreads();

  const float* xb0 = g_xproj + (size_t)b0 * TT * HH + j0;
  const float* xb1 = g_xproj + (size_t)b1 * TT * HH + j0;
  const ulonglong2* sWa =
      reinterpret_cast<const ulonglong2*>(sW4 + (KH * 2 + 0) * 6 * 128);
  const ulonglong2* sWb =
      reinterpret_cast<const ulonglong2*>(sW4 + (KH * 2 + 1) * 6 * 128);
  const ulonglong2* hp0 = reinterpret_cast<const ulonglong2*>(sh0 + kb);
  const ulonglong2* hp1 = reinterpret_cast<const ulonglong2*>(sh1 + kb);

  for (int t = 0; t < TT; ++t) {
    float2 xq0, xq1;
    if (KH == 0) {
      xq0 = __ldg(reinterpret_cast<const float2*>(xb0 + (size_t)t * HH));
      xq1 = __ldg(reinterpret_cast<const float2*>(xb1 + (size_t)t * HH));
    }
    ull acc00 = 0ull, acc10 = 0ull, acc01 = 0ull, acc11 = 0ull;
    // register-W part: k = kb .. kb+39
    #pragma unroll
    for (int q = 0; q < 10; ++q) {
      ulonglong2 v0 = hp0[q];
      ulonglong2 v1 = hp1[q];
      acc00 = ffma2(wA[2 * q],     v0.x, acc00);
      acc10 = ffma2(wB[2 * q],     v0.x, acc10);
      acc01 = ffma2(wA[2 * q],     v1.x, acc01);
      acc11 = ffma2(wB[2 * q],     v1.x, acc11);
      acc00 = ffma2(wA[2 * q + 1], v0.y, acc00);
      acc10 = ffma2(wB[2 * q + 1], v0.y, acc10);
      acc01 = ffma2(wA[2 * q + 1], v1.y, acc01);
      acc11 = ffma2(wB[2 * q + 1], v1.y, acc11);
    }
    // smem-W part: k = kb+40 .. kb+63
    #pragma unroll
    for (int q = 0; q < 6; ++q) {
      ulonglong2 v0 = hp0[10 + q];
      ulonglong2 v1 = hp1[10 + q];
      ulonglong2 wa = sWa[q * 128 + JP];
      ulonglong2 wb = sWb[q * 128 + JP];
      acc00 = ffma2(wa.x, v0.x, acc00);
      acc10 = ffma2(wb.x, v0.x, acc10);
      acc01 = ffma2(wa.x, v1.x, acc01);
      acc11 = ffma2(wb.x, v1.x, acc11);
      acc00 = ffma2(wa.y, v0.y, acc00);
      acc10 = ffma2(wb.y, v0.y, acc10);
      acc01 = ffma2(wa.y, v1.y, acc01);
      acc11 = ffma2(wb.y, v1.y, acc11);
    }

    float p00 = hsum2(acc00);
    float p10 = hsum2(acc10);
    float p01 = hsum2(acc01);
    float p11 = hsum2(acc11);

    if (KH) {
      spart[(KH - 1) * 128 + JP] = make_float4(p00, p10, p01, p11);
    }
    __syncthreads();
    if (KH == 0) {
      float4 pa = spart[JP];
      float4 pb = spart[128 + JP];
      float4 pc = spart[256 + JP];
      p00 += pa.x + pb.x + pc.x + xq0.x;
      p10 += pa.y + pb.y + pc.y + xq0.y;
      p01 += pa.z + pb.z + pc.z + xq1.x;
      p11 += pa.w + pb.w + pc.w + xq1.y;
      h00 = 0.8f * h00 + 0.2f * fmaxf(p00, 0.0f);
      h10 = 0.8f * h10 + 0.2f * fmaxf(p10, 0.0f);
      h01 = 0.8f * h01 + 0.2f * fmaxf(p01, 0.0f);
      h11 = 0.8f * h11 + 0.2f * fmaxf(p11, 0.0f);
      *reinterpret_cast<float2*>(sh0 + j0) = make_float2(h00, h10);
      *reinterpret_cast<float2*>(sh1 + j0) = make_float2(h01, h11);
    }
    __syncthreads();
  }

  // -------- epilogue --------
  float* out_actor  = out;                 // [B][A]
  float* out_critic = out + BB * AA;       // [B]
  float* out_hx     = out + BB * AA + BB;  // [B][H]

  if (tid < HH) {
    out_hx[b0 * HH + tid] = sh0[tid];
    out_hx[b1 * HH + tid] = sh1[tid];
  }

  const int wid = tid >> 5, lane = tid & 31;
  if (wid < AA) {
    float pa0 = 0.f, pa1 = 0.f;
    for (int j = lane; j < HH; j += 32) {
      float wa = W_actor[wid * HH + j];
      pa0 += wa * sh0[j];
      pa1 += wa * sh1[j];
    }
    #pragma unroll
    for (int off = 16; off; off >>= 1) {
      pa0 += __shfl_down_sync(0xffffffffu, pa0, off);
      pa1 += __shfl_down_sync(0xffffffffu, pa1, off);
    }
    if (lane == 0) {
      out_actor[b0 * AA + wid] = pa0;
      out_actor[b1 * AA + wid] = pa1;
    }
  }
  if (wid == 8) {
    float pc0 = 0.f, pc1 = 0.f;
    for (int j = lane; j < HH; j += 32) {
      float wc = W_critic[j];
      pc0 += wc * sh0[j];
      pc1 += wc * sh1[j];
    }
    #pragma unroll
    for (int off = 16; off; off >>= 1) {
      pc0 += __shfl_down_sync(0xffffffffu, pc0, off);
      pc1 += __shfl_down_sync(0xffffffffu, pc1, off);
    }
    if (lane == 0) {
      out_critic[b0] = pc0;
      out_critic[b1] = pc1;
    }
  }
}

// ---------------------------------------------------------------------------
extern "C" void kernel_launch(void* const* d_in, const int* in_sizes, int n_in,
                              void* d_out, int out_size) {
  const float* x        = (const float*)d_in[0];
  const float* hx       = (const float*)d_in[1];
  const float* W_ih     = (const float*)d_in[2];
  const float* W_hh     = (const float*)d_in[3];
  const float* W_actor  = (const float*)d_in[4];
  const float* W_critic = (const float*)d_in[5];
  float* out = (float*)d_out;

  const int smem1 = 2 * 2048 * (int)sizeof(float);                     // 16KB
  const int smem2 = (24576 + 256 + 256 + 3 * 128 * 4) * (int)sizeof(float);  // 106496

  cudaFuncSetAttribute(xproj_kernel,
                       cudaFuncAttributeMaxDynamicSharedMemorySize, smem1);
  cudaFuncSetAttribute(recurrence_kernel,
                       cudaFuncAttributeMaxDynamicSharedMemorySize, smem2);

  xproj_kernel<<<(BB * TT) / 256, 256, smem1>>>(x, W_ih);
  recurrence_kernel<<<BB / 2, 512, smem2>>>(hx, W_hh, W_actor, W_critic, out);
}